// round 1
// baseline (speedup 1.0000x reference)
#include <cuda_runtime.h>

// Problem constants (match reference module hyperparameters)
#define NP   64     // patch size
#define CH   4      // channels (GRIDSIZE^2)
#define PAD  192    // padded canvas
#define XPT  4      // output pixels per thread (float4 store)
#define TPB  256    // threads per block

// out[b, y, x] = sum_c bilinear(patch_c centered in canvas, y - dy_c, x - dx_c)
// patch coords: sy = y - 64 - dy_c ; sx = x - 64 - dx_c ; zero fill outside [0,64)
__global__ __launch_bounds__(TPB)
void reassemble_kernel(const float* __restrict__ patches,
                       const float* __restrict__ pos,
                       float* __restrict__ out)
{
    const int t  = blockIdx.x * TPB + threadIdx.x;   // 0 .. 9215 (per-b pixel/4 index)
    const int b  = blockIdx.y;
    const int x4 = t % (PAD / XPT);                  // 0..47
    const int y  = t / (PAD / XPT);                  // 0..191
    const int x0 = x4 * XPT;

    // per-b sub-pixel offsets: pos layout (B,1,2,C): dx at b*8+c, dy at b*8+4+c
    const float* pb_pos = pos + (size_t)b * 2 * CH;

    float acc0 = 0.f, acc1 = 0.f, acc2 = 0.f, acc3 = 0.f;
    const float* pb = patches + (size_t)b * NP * NP * CH;

    const float yf  = (float)y  - 64.0f;
    const float x0f = (float)x0 - 64.0f;

    #pragma unroll
    for (int c = 0; c < CH; c++) {
        const float dxc = __ldg(pb_pos + c);
        const float dyc = __ldg(pb_pos + CH + c);

        const float sy  = yf - dyc;
        const float fyf = floorf(sy);
        const int   iy  = (int)fyf;
        if (iy < -1 || iy > NP - 1) continue;        // both tap rows outside patch
        const float wy = sy - fyf;

        const float sx  = x0f - dxc;
        const float fxf = floorf(sx);
        const int   ix  = (int)fxf;
        if (ix > NP - 1 || ix + XPT < 0) continue;   // all tap cols outside patch
        const float wx = sx - fxf;                   // same fraction for all 4 pixels

        const bool r0v = (iy >= 0);                  // iy <= 63 guaranteed
        const bool r1v = (iy + 1 <= NP - 1);         // iy+1 >= 0 guaranteed (iy >= -1)
        const float* rowt = pb + ((size_t)iy       * NP) * CH + c;
        const float* rowb = pb + ((size_t)(iy + 1) * NP) * CH + c;

        float vt[XPT + 1], vb[XPT + 1];
        #pragma unroll
        for (int k = 0; k <= XPT; k++) {
            const int col = ix + k;
            const bool cv = (col >= 0 && col < NP);
            vt[k] = (r0v && cv) ? __ldg(rowt + col * CH) : 0.0f;
            vb[k] = (r1v && cv) ? __ldg(rowb + col * CH) : 0.0f;
        }

        const float omwx = 1.0f - wx;
        const float omwy = 1.0f - wy;
        const float t0 = vt[0] * omwx + vt[1] * wx;
        const float t1 = vt[1] * omwx + vt[2] * wx;
        const float t2 = vt[2] * omwx + vt[3] * wx;
        const float t3 = vt[3] * omwx + vt[4] * wx;
        const float b0 = vb[0] * omwx + vb[1] * wx;
        const float b1 = vb[1] * omwx + vb[2] * wx;
        const float b2 = vb[2] * omwx + vb[3] * wx;
        const float b3 = vb[3] * omwx + vb[4] * wx;

        acc0 += t0 * omwy + b0 * wy;
        acc1 += t1 * omwy + b1 * wy;
        acc2 += t2 * omwy + b2 * wy;
        acc3 += t3 * omwy + b3 * wy;
    }

    float4 o;
    o.x = acc0; o.y = acc1; o.z = acc2; o.w = acc3;
    *reinterpret_cast<float4*>(out + ((size_t)b * PAD + y) * PAD + x0) = o;
}

extern "C" void kernel_launch(void* const* d_in, const int* in_sizes, int n_in,
                              void* d_out, int out_size) {
    const float* patches = (const float*)d_in[0];   // (B, 64, 64, 4) fp32
    const float* pos     = (const float*)d_in[1];   // (B, 1, 2, 4)  fp32
    float* out           = (float*)d_out;           // (B, 192, 192, 1) fp32

    const int B = out_size / (PAD * PAD);           // 512
    // per-b: 192*192/4 = 9216 threads = 36 blocks of 256
    dim3 grid((PAD * PAD / XPT) / TPB, B);
    reassemble_kernel<<<grid, TPB>>>(patches, pos, out);
}